// round 1
// baseline (speedup 1.0000x reference)
#include <cuda_runtime.h>
#include <math.h>

#define Bc 16
#define Lc 2048
#define Hc 512
#define Pc 64
#define BLc (Bc*Lc)
#define TQ 128
#define TK 64

// Scratch (allocation-free rule: __device__ globals)
__device__ float g_q[BLc*Pc];
__device__ float g_k[BLc*Pc];
__device__ float g_v[BLc*Pc];
__device__ float g_w[BLc*Pc];

// ---------------------------------------------------------------------------
// Kernel A: q/k/v = query @ W + b.  Block: 128 rows x 64 cols, blockIdx.y picks
// which of {Wq,Wk,Wv}. 256 threads, 8x4 per-thread register tile.
// ---------------------------------------------------------------------------
__global__ __launch_bounds__(256) void qkv_kernel(
    const float* __restrict__ query,
    const float* __restrict__ Wq, const float* __restrict__ bq,
    const float* __restrict__ Wk, const float* __restrict__ bk,
    const float* __restrict__ Wv, const float* __restrict__ bv)
{
    __shared__ float At[32][132];   // transposed A tile [k][row], padded
    __shared__ float Wt[32][64];    // W tile [k][col]

    const int tid = threadIdx.x;
    const int tx = tid & 15, ty = tid >> 4;
    const int r0 = blockIdx.x * 128;
    const int which = blockIdx.y;
    const float* W    = (which == 0) ? Wq : (which == 1) ? Wk : Wv;
    const float* bias = (which == 0) ? bq : (which == 1) ? bk : bv;
    float* dst        = (which == 0) ? g_q : (which == 1) ? g_k : g_v;

    float acc[8][4];
    #pragma unroll
    for (int i = 0; i < 8; i++)
        #pragma unroll
        for (int j = 0; j < 4; j++) acc[i][j] = 0.f;

    for (int k0 = 0; k0 < Hc; k0 += 32) {
        __syncthreads();
        // load A transposed (coalesced gmem read, scatter smem write)
        #pragma unroll
        for (int e = tid; e < 128*32; e += 256) {
            int kk = e & 31, row = e >> 5;
            At[kk][row] = query[(size_t)(r0 + row) * Hc + k0 + kk];
        }
        // load W tile
        #pragma unroll
        for (int e = tid; e < 32*64; e += 256) {
            int kk = e >> 6, c = e & 63;
            Wt[kk][c] = W[(size_t)(k0 + kk) * Pc + c];
        }
        __syncthreads();
        #pragma unroll 8
        for (int kk = 0; kk < 32; kk++) {
            const float4 a0 = *(const float4*)&At[kk][8*ty];
            const float4 a1 = *(const float4*)&At[kk][8*ty + 4];
            const float4 w  = *(const float4*)&Wt[kk][4*tx];
            const float av[8] = {a0.x,a0.y,a0.z,a0.w,a1.x,a1.y,a1.z,a1.w};
            const float wv[4] = {w.x,w.y,w.z,w.w};
            #pragma unroll
            for (int i = 0; i < 8; i++)
                #pragma unroll
                for (int j = 0; j < 4; j++)
                    acc[i][j] = fmaf(av[i], wv[j], acc[i][j]);
        }
    }

    const float4 bb = *(const float4*)&bias[4*tx];
    #pragma unroll
    for (int i = 0; i < 8; i++) {
        const int g = r0 + 8*ty + i;
        float4 o;
        o.x = acc[i][0] + bb.x; o.y = acc[i][1] + bb.y;
        o.z = acc[i][2] + bb.z; o.w = acc[i][3] + bb.w;
        *(float4*)&dst[(size_t)g * Pc + 4*tx] = o;
    }
}

// ---------------------------------------------------------------------------
// Kernel B: flash attention, fp32, online softmax.
// Block: 128 q-rows (one b), loops over 2048 keys in 64-key tiles.
// 256 threads as 16(ty: 8 rows each) x 16(tx: 4 cols each).
// NOTE: attention_mask adds a per-(b,q) constant over the key axis -> softmax
// invariant -> mask ignored (exact).
// ---------------------------------------------------------------------------
__global__ __launch_bounds__(256) void attn_kernel()
{
    extern __shared__ float sm[];
    float* Qt = sm;                      // [64][132] transposed Q (p-major)
    float* Kt = Qt + 64*132;             // [64][68]  transposed K (p-major)
    float* Vs = Kt + 64*68;              // [64][64]  V natural [key][p]
    float* Ps = Vs + 64*64;              // [128][68] P tile [row][key]

    const int tid = threadIdx.x;
    const int tx = tid & 15, ty = tid >> 4;
    const int b  = blockIdx.y;
    const int q0 = blockIdx.x * TQ;
    const size_t base = (size_t)b * Lc * Pc;

    // load Q transposed
    for (int e = tid; e < TQ*Pc; e += 256) {
        int p = e & 63, row = e >> 6;
        Qt[p*132 + row] = g_q[base + (size_t)(q0 + row) * Pc + p];
    }

    float o[8][4], m2[8], l[8];
    #pragma unroll
    for (int i = 0; i < 8; i++) {
        m2[i] = -1e30f; l[i] = 0.f;
        #pragma unroll
        for (int j = 0; j < 4; j++) o[i][j] = 0.f;
    }

    const float scale2 = 0.125f * 1.4426950408889634f;  // (1/sqrt(64))*log2(e)

    for (int kt = 0; kt < Lc; kt += TK) {
        __syncthreads();
        // load K transposed
        for (int e = tid; e < TK*Pc; e += 256) {
            int p = e & 63, row = e >> 6;
            Kt[p*68 + row] = g_k[base + (size_t)(kt + row) * Pc + p];
        }
        // load V (straight copy, float4)
        {
            const float4* src = (const float4*)&g_v[base + (size_t)kt * Pc];
            for (int e4 = tid; e4 < TK*Pc/4; e4 += 256)
                ((float4*)Vs)[e4] = src[e4];
        }
        __syncthreads();

        // S = Q K^T (raw, unscaled)
        float s[8][4];
        #pragma unroll
        for (int i = 0; i < 8; i++)
            #pragma unroll
            for (int j = 0; j < 4; j++) s[i][j] = 0.f;

        #pragma unroll 8
        for (int kk = 0; kk < 64; kk++) {
            const float4 a0 = *(const float4*)(Qt + kk*132 + 8*ty);
            const float4 a1 = *(const float4*)(Qt + kk*132 + 8*ty + 4);
            const float4 kv = *(const float4*)(Kt + kk*68 + 4*tx);
            const float av[8] = {a0.x,a0.y,a0.z,a0.w,a1.x,a1.y,a1.z,a1.w};
            const float kw[4] = {kv.x,kv.y,kv.z,kv.w};
            #pragma unroll
            for (int i = 0; i < 8; i++)
                #pragma unroll
                for (int j = 0; j < 4; j++)
                    s[i][j] = fmaf(av[i], kw[j], s[i][j]);
        }

        // online softmax update (per row; stats replicated across the 16 tx lanes)
        #pragma unroll
        for (int i = 0; i < 8; i++) {
            float mt = fmaxf(fmaxf(s[i][0], s[i][1]), fmaxf(s[i][2], s[i][3]));
            #pragma unroll
            for (int off = 8; off; off >>= 1)
                mt = fmaxf(mt, __shfl_xor_sync(0xffffffffu, mt, off));
            mt *= scale2;                       // scale2 > 0: max commutes
            const float mn = fmaxf(m2[i], mt);
            const float alpha = exp2f(m2[i] - mn);
            m2[i] = mn;
            float rs = 0.f;
            #pragma unroll
            for (int j = 0; j < 4; j++) {
                s[i][j] = exp2f(fmaf(s[i][j], scale2, -mn));
                rs += s[i][j];
            }
            #pragma unroll
            for (int off = 8; off; off >>= 1)
                rs += __shfl_xor_sync(0xffffffffu, rs, off);
            l[i] = l[i] * alpha + rs;
            #pragma unroll
            for (int j = 0; j < 4; j++) o[i][j] *= alpha;
        }

        // write P tile
        #pragma unroll
        for (int i = 0; i < 8; i++) {
            float4 pv; pv.x = s[i][0]; pv.y = s[i][1]; pv.z = s[i][2]; pv.w = s[i][3];
            *(float4*)(Ps + (8*ty + i)*68 + 4*tx) = pv;
        }
        __syncthreads();

        // O += P @ V
        #pragma unroll 2
        for (int k4 = 0; k4 < 16; k4++) {
            float vvf[4][4];
            #pragma unroll
            for (int c = 0; c < 4; c++) {
                const float4 v4 = *(const float4*)(Vs + (4*k4 + c)*64 + 4*tx);
                vvf[c][0] = v4.x; vvf[c][1] = v4.y; vvf[c][2] = v4.z; vvf[c][3] = v4.w;
            }
            #pragma unroll
            for (int i = 0; i < 8; i++) {
                const float4 p4 = *(const float4*)(Ps + (8*ty + i)*68 + 4*k4);
                const float pf[4] = {p4.x, p4.y, p4.z, p4.w};
                #pragma unroll
                for (int c = 0; c < 4; c++)
                    #pragma unroll
                    for (int j = 0; j < 4; j++)
                        o[i][j] = fmaf(pf[c], vvf[c][j], o[i][j]);
            }
        }
    }

    // normalize + store weighted
    #pragma unroll
    for (int i = 0; i < 8; i++) {
        const float inv = 1.f / l[i];
        float4 ov;
        ov.x = o[i][0]*inv; ov.y = o[i][1]*inv; ov.z = o[i][2]*inv; ov.w = o[i][3]*inv;
        *(float4*)&g_w[base + (size_t)(q0 + 8*ty + i) * Pc + 4*tx] = ov;
    }
}

// ---------------------------------------------------------------------------
// Kernel C: out = weighted @ Wo + bo.  Block: 64 rows x 64 cols, K=64 full.
// ---------------------------------------------------------------------------
__global__ __launch_bounds__(256) void out_kernel(
    const float* __restrict__ Wo, const float* __restrict__ bo,
    float* __restrict__ out)
{
    __shared__ float At[64][68];   // transposed weighted tile [p][row]
    __shared__ float Wt[64][64];   // Wo slice [p][col]

    const int tid = threadIdx.x;
    const int tx = tid & 15, ty = tid >> 4;
    const int r0 = blockIdx.x * 64;
    const int c0 = blockIdx.y * 64;

    for (int e = tid; e < 64*64; e += 256) {
        int p = e & 63, row = e >> 6;
        At[p][row] = g_w[(size_t)(r0 + row) * Pc + p];
    }
    for (int e = tid; e < 64*64; e += 256) {
        int p = e >> 6, c = e & 63;
        Wt[p][c] = Wo[(size_t)p * Hc + c0 + c];
    }
    __syncthreads();

    float acc[4][4];
    #pragma unroll
    for (int i = 0; i < 4; i++)
        #pragma unroll
        for (int j = 0; j < 4; j++) acc[i][j] = 0.f;

    #pragma unroll 16
    for (int p = 0; p < 64; p++) {
        const float4 a = *(const float4*)&At[p][4*ty];
        const float4 w = *(const float4*)&Wt[p][4*tx];
        const float av[4] = {a.x,a.y,a.z,a.w};
        const float wv[4] = {w.x,w.y,w.z,w.w};
        #pragma unroll
        for (int i = 0; i < 4; i++)
            #pragma unroll
            for (int j = 0; j < 4; j++)
                acc[i][j] = fmaf(av[i], wv[j], acc[i][j]);
    }

    const float4 bb = *(const float4*)&bo[c0 + 4*tx];
    #pragma unroll
    for (int i = 0; i < 4; i++) {
        float4 ov;
        ov.x = acc[i][0] + bb.x; ov.y = acc[i][1] + bb.y;
        ov.z = acc[i][2] + bb.z; ov.w = acc[i][3] + bb.w;
        *(float4*)&out[(size_t)(r0 + 4*ty + i) * Hc + c0 + 4*tx] = ov;
    }
}

// ---------------------------------------------------------------------------
extern "C" void kernel_launch(void* const* d_in, const int* in_sizes, int n_in,
                              void* d_out, int out_size)
{
    const float* query = (const float*)d_in[0];
    // d_in[1] = attention_mask: per-row constant shift over softmax axis -> no-op
    const float* Wq = (const float*)d_in[2];
    const float* bq = (const float*)d_in[3];
    const float* Wk = (const float*)d_in[4];
    const float* bk = (const float*)d_in[5];
    const float* Wv = (const float*)d_in[6];
    const float* bv = (const float*)d_in[7];
    const float* Wo = (const float*)d_in[8];
    const float* bo = (const float*)d_in[9];
    float* out = (float*)d_out;

    qkv_kernel<<<dim3(BLc/128, 3), 256>>>(query, Wq, bq, Wk, bk, Wv, bv);

    const size_t smemB = (size_t)(64*132 + 64*68 + 64*64 + 128*68) * sizeof(float); // 102400
    cudaFuncSetAttribute(attn_kernel, cudaFuncAttributeMaxDynamicSharedMemorySize, (int)smemB);
    attn_kernel<<<dim3(Lc/TQ, Bc), 256, smemB>>>();

    out_kernel<<<dim3(BLc/64, Hc/64), 256>>>(Wo, bo, out);
}